// round 13
// baseline (speedup 1.0000x reference)
#include <cuda_runtime.h>
#define HDIM 512
#define BATCH 256
#define TLEN 512
#define NSTEPS 511
#define FC1_N 1024
#define FC2_N 32000
typedef unsigned long long u64;

// -------- persistent device scratch --------
__device__ float g_wt[32 * 512 * 64];    // 4MB W: [kx][kk][kcol16][gate4] f32
__device__ u64   g_hp[2][512 * 128];     // h batch-pairs [k][pair], dbl-buffered
__device__ float g_hlast[BATCH * HDIM];
__device__ float g_z[BATCH * FC1_N];
__device__ unsigned int g_flag[128];     // write flags [by][kx]
__device__ unsigned int g_rflag[128];    // read-done flags [by][kx]
__device__ int g_dummy;

__device__ __forceinline__ u64 pack2(float lo, float hi) {
    u64 r; asm("mov.b64 %0, {%1, %2};" : "=l"(r) : "f"(lo), "f"(hi)); return r;
}
__device__ __forceinline__ void unpack2(u64 v, float& lo, float& hi) {
    asm("mov.b64 {%0, %1}, %2;" : "=f"(lo), "=f"(hi) : "l"(v));
}
__device__ __forceinline__ void ffma2(u64& d, u64 a, u64 b) {
    asm("fma.rn.f32x2 %0, %1, %2, %0;" : "+l"(d) : "l"(a), "l"(b));
}
__device__ __forceinline__ ulonglong2 ldcg2(const u64* p) {
    ulonglong2 v;
    asm volatile("ld.global.cg.v2.u64 {%0,%1}, [%2];" : "=l"(v.x), "=l"(v.y) : "l"(p));
    return v;
}
__device__ __forceinline__ void stcg1(u64* p, u64 a) {
    asm volatile("st.global.cg.u64 [%0], %1;" :: "l"(p), "l"(a) : "memory");
}
__device__ __forceinline__ unsigned int ld_acq(const unsigned int* p) {
    unsigned int v;
    asm volatile("ld.global.acquire.gpu.b32 %0, [%1];" : "=r"(v) : "l"(p));
    return v;
}
__device__ __forceinline__ void st_rel(unsigned int* p, unsigned int v) {
    asm volatile("st.global.release.gpu.b32 [%0], %1;" :: "l"(p), "r"(v) : "memory");
}
// fast activations (MUFU; validated R12: rel_err unchanged)
__device__ __forceinline__ float sigmoidf_(float x) {
    return 1.0f / (1.0f + __expf(-x));
}
__device__ __forceinline__ float tanhf_(float x) {
    return 1.0f - 2.0f / (__expf(2.0f * x) + 1.0f);
}

// ---- W transform (R9-proven) ----
__global__ void prep_w(const float* __restrict__ w) {
    int tid = blockIdx.x * blockDim.x + threadIdx.x;   // 0..1048575
    int g = tid & 3, kcol = (tid >> 2) & 15, kk = (tid >> 6) & 511, kx = tid >> 15;
    g_wt[tid] = w[(size_t)(g * HDIM + kx * 16 + kcol) * HDIM + kk];
}

__global__ void prep_misc() {
    int i = blockIdx.x * blockDim.x + threadIdx.x;
    int n = gridDim.x * blockDim.x;
    for (int j = i; j < 512 * 128; j += n) g_hp[0][j] = 0ull;
    if (i < 128) { g_flag[i] = 0u; g_rflag[i] = 0u; }
}

// spacer: puts lstm_persist at launch #4 (the ncu capture slot)
__global__ void nopk(int v) { if (v == 12345) g_dummy = v; }

// ============================================================================
// Persistent LSTM (R10/R12 microkernel + chunk-gated producer flags).
// 128 CTAs (32 kx x 4 by) x 128 thr, 1 CTA/SM. W resident in smem (131kB).
// Thread: 1 kcol x 4 gates x 4 batch-pairs; per kk: LDS.128(w) + 4 LDS.64(h)
// + 4 dup movs + 16 FFMA2 (1.5 B/MAC). c in registers.
// Sync: wflag waits split (kx 0-15 at prologue, kx 16-31 at kc=7, overlapped
// with compute); rflag (read-done) guards the WAR on the h double buffer.
// ============================================================================
#define SW_F 32768                        // 512*64 f32
#define SMEMB (SW_F * 4 + 2 * 1024 * 8)   // 147456 B
__global__ __launch_bounds__(128, 1)
void lstm_persist(const int* __restrict__ trg,
                  const float* __restrict__ w_ih,
                  const float* __restrict__ b_ih,
                  const float* __restrict__ b_hh)
{
    extern __shared__ unsigned char smraw[];
    float* sW = (float*)smraw;                    // [512][16][4]
    u64*   sH = (u64*)(smraw + SW_F * 4);         // [2][32 kk][32 pairs]

    const int t  = threadIdx.x;
    const int kx = blockIdx.x & 31, by = blockIdx.x >> 5;
    const int tk = t >> 3, tb = t & 7;
    const int kcol = kx * 16 + tk;
    const int bp0 = by * 32;

    // load W slice once (coalesced)
    {
        const float4* ws = (const float4*)(g_wt + (size_t)kx * SW_F);
        float4* wd = (float4*)sW;
        for (int i = t; i < SW_F / 4; i += 128) wd[i] = ws[i];
    }
    float bias[4], wih[4];
#pragma unroll
    for (int g = 0; g < 4; g++) {
        int r = g * HDIM + kcol;
        bias[g] = b_ih[r] + b_hh[r];
        wih[g]  = w_ih[r];
    }
    u64 cst[4] = {0ull, 0ull, 0ull, 0ull};
    __syncthreads();

#pragma unroll 1
    for (int s = 0; s < NSTEPS; s++) {
        const u64* __restrict__ hin  = g_hp[s & 1];
        u64*       __restrict__ hout = g_hp[(s & 1) ^ 1];

        // gate chunks 0-7: wait producers kx 0..15 only
        if (s > 0) {
            if (t < 16) { while (ld_acq(&g_flag[by * 32 + t]) < (unsigned)s) { } }
            __syncthreads();
        }

        // acc init: bias + x * w_ih
        u64 acc[4][4];
#pragma unroll
        for (int j = 0; j < 4; j++) {
            int b = (bp0 + tb + 8 * j) * 2;
            float x0 = (float)__ldg(trg + b * TLEN + s);
            float x1 = (float)__ldg(trg + (b + 1) * TLEN + s);
#pragma unroll
            for (int g = 0; g < 4; g++)
                acc[g][j] = pack2(fmaf(x0, wih[g], bias[g]), fmaf(x1, wih[g], bias[g]));
        }

        // prologue: chunk 0 -> buf 0
        ulonglong2 pf[4];
#pragma unroll
        for (int q = 0; q < 4; q++) {
            int idx = q * 128 + t;
            pf[q] = ldcg2(hin + (size_t)(idx >> 4) * 128 + bp0 + (idx & 15) * 2);
        }
#pragma unroll
        for (int q = 0; q < 4; q++) {
            int idx = q * 128 + t;
            *(ulonglong2*)(sH + (idx >> 4) * 32 + (idx & 15) * 2) = pf[q];
        }
        __syncthreads();

#pragma unroll 1
        for (int kc = 0; kc < 16; kc++) {
            // gate chunks 8-15: wait producers kx 16..31 (overlapped: ~11k cyc
            // of compute has elapsed; normally satisfied instantly)
            if (kc == 8 && s > 0) {
                if (t < 16) { while (ld_acq(&g_flag[by * 32 + 16 + t]) < (unsigned)s) { } }
                __syncthreads();
            }
            if (kc < 15) {
#pragma unroll
                for (int q = 0; q < 4; q++) {
                    int idx = q * 128 + t;
                    pf[q] = ldcg2(hin + (size_t)((kc + 1) * 32 + (idx >> 4)) * 128
                                  + bp0 + (idx & 15) * 2);
                }
            }
            const u64*   Hb = sH + (kc & 1) * 1024;
            const float* Wb = sW + (size_t)kc * 2048 + tk * 4;

            float4 wv = *(const float4*)(Wb);
            u64 h0 = Hb[tb], h1 = Hb[tb + 8], h2 = Hb[tb + 16], h3 = Hb[tb + 24];
#pragma unroll
            for (int kk = 0; kk < 32; kk++) {
                float4 wn;
                u64 n0, n1, n2, n3;
                if (kk < 31) {
                    wn = *(const float4*)(Wb + (kk + 1) * 64);
                    const u64* Hn = Hb + (kk + 1) * 32;
                    n0 = Hn[tb]; n1 = Hn[tb + 8]; n2 = Hn[tb + 16]; n3 = Hn[tb + 24];
                }
                u64 wd0 = pack2(wv.x, wv.x), wd1 = pack2(wv.y, wv.y);
                u64 wd2 = pack2(wv.z, wv.z), wd3 = pack2(wv.w, wv.w);
                ffma2(acc[0][0], wd0, h0); ffma2(acc[1][0], wd1, h0);
                ffma2(acc[2][0], wd2, h0); ffma2(acc[3][0], wd3, h0);
                ffma2(acc[0][1], wd0, h1); ffma2(acc[1][1], wd1, h1);
                ffma2(acc[2][1], wd2, h1); ffma2(acc[3][1], wd3, h1);
                ffma2(acc[0][2], wd0, h2); ffma2(acc[1][2], wd1, h2);
                ffma2(acc[2][2], wd2, h2); ffma2(acc[3][2], wd3, h2);
                ffma2(acc[0][3], wd0, h3); ffma2(acc[1][3], wd1, h3);
                ffma2(acc[2][3], wd2, h3); ffma2(acc[3][3], wd3, h3);
                if (kk < 31) { wv = wn; h0 = n0; h1 = n1; h2 = n2; h3 = n3; }
            }
            if (kc < 15) {
#pragma unroll
                for (int q = 0; q < 4; q++) {
                    int idx = q * 128 + t;
                    *(ulonglong2*)(sH + ((kc + 1) & 1) * 1024
                                   + (idx >> 4) * 32 + (idx & 15) * 2) = pf[q];
                }
            }
            __syncthreads();
        }

        // all global reads of this step's input retired -> post read-done
        if (t == 0) st_rel(&g_rflag[by * 32 + kx], (unsigned)(s + 1));

        // WAR guard: before overwriting the buffer step s-1 readers used,
        // ensure all 32 group CTAs finished reading it (posted a step ago,
        // so this is effectively free)
        if (s > 0) {
            if (t < 32) { while (ld_acq(&g_rflag[by * 32 + t]) < (unsigned)s) { } }
            __syncthreads();
        }

        // ---- pointwise (i,f,g,o) ----
#pragma unroll
        for (int j = 0; j < 4; j++) {
            float i0, i1, f0, f1, g0, g1, o0, o1, c0, c1;
            unpack2(acc[0][j], i0, i1); unpack2(acc[1][j], f0, f1);
            unpack2(acc[2][j], g0, g1); unpack2(acc[3][j], o0, o1);
            unpack2(cst[j], c0, c1);
            i0 = sigmoidf_(i0); f0 = sigmoidf_(f0); g0 = tanhf_(g0); o0 = sigmoidf_(o0);
            i1 = sigmoidf_(i1); f1 = sigmoidf_(f1); g1 = tanhf_(g1); o1 = sigmoidf_(o1);
            c0 = fmaf(f0, c0, i0 * g0);
            c1 = fmaf(f1, c1, i1 * g1);
            cst[j] = pack2(c0, c1);
            float h0 = o0 * tanhf_(c0);
            float h1 = o1 * tanhf_(c1);
            stcg1(hout + (size_t)kcol * 128 + bp0 + tb + 8 * j, pack2(h0, h1));
            if (s == NSTEPS - 1) {
                int b = (bp0 + tb + 8 * j) * 2;
                g_hlast[(size_t)b * HDIM + kcol]       = h0;
                g_hlast[(size_t)(b + 1) * HDIM + kcol] = h1;
            }
        }

        if (s < NSTEPS - 1) {
            __syncthreads();
            if (t == 0) {
                __threadfence();
                st_rel(&g_flag[by * 32 + kx], (unsigned)(s + 1));
            }
        }
    }
}

// ============================================================================
// fc1 head (R3-proven fc_gemm): C = A @ W^T + bias, ReLU.
// ============================================================================
__global__ __launch_bounds__(256)
void fc_gemm(int asel, const float* __restrict__ W, const float* __restrict__ bias,
             float* __restrict__ C, int K, int N, int do_relu)
{
    __shared__ float  sW[32 * 128];
    __shared__ float2 sH2[32 * 33];
    const float* __restrict__ A = (asel == 0) ? &g_hlast[0] : &g_z[0];
    const int t = threadIdx.x, n0 = blockIdx.x * 128, m0 = blockIdx.y * 32;
    const int cc = t & 15, bi0 = (t >> 4) * 2;

    u64 acc[2][4];
#pragma unroll
    for (int g = 0; g < 4; g++) {
        float2 b2 = *(const float2*)(bias + n0 + g * 32 + 2 * cc);
        acc[0][g] = pack2(b2.x, b2.y);
        acc[1][g] = pack2(b2.x, b2.y);
    }
    const int r128 = t >> 1, hf = t & 1;
    const float4* __restrict__ Wrow = (const float4*)(W + (size_t)(n0 + r128) * K);
    const int hbi = t >> 3, hk0 = (t & 7) * 4;
    const u64* sWu = (const u64*)sW;
    const u64* sHu = (const u64*)sH2;

    for (int kc = 0; kc < K; kc += 32) {
        if (kc) __syncthreads();
#pragma unroll
        for (int q = 0; q < 4; q++) {
            float4 v = Wrow[(kc + hf * 16) / 4 + q];
            int kl = hf * 16 + q * 4;
            sW[(kl + 0) * 128 + r128] = v.x;
            sW[(kl + 1) * 128 + r128] = v.y;
            sW[(kl + 2) * 128 + r128] = v.z;
            sW[(kl + 3) * 128 + r128] = v.w;
        }
        float4 hv = *(const float4*)(A + (size_t)(m0 + hbi) * K + kc + hk0);
        sH2[(hk0 + 0) * 33 + hbi] = make_float2(hv.x, hv.x);
        sH2[(hk0 + 1) * 33 + hbi] = make_float2(hv.y, hv.y);
        sH2[(hk0 + 2) * 33 + hbi] = make_float2(hv.z, hv.z);
        sH2[(hk0 + 3) * 33 + hbi] = make_float2(hv.w, hv.w);
        __syncthreads();
#pragma unroll 8
        for (int kk = 0; kk < 32; kk++) {
            u64 h0 = sHu[kk * 33 + bi0];
            u64 h1 = sHu[kk * 33 + bi0 + 1];
#pragma unroll
            for (int g = 0; g < 4; g++) {
                u64 w = sWu[kk * 64 + g * 16 + cc];
                ffma2(acc[0][g], w, h0);
                ffma2(acc[1][g], w, h1);
            }
        }
    }
#pragma unroll
    for (int bb = 0; bb < 2; bb++) {
        int m = m0 + bi0 + bb;
#pragma unroll
        for (int g = 0; g < 4; g++) {
            float lo, hi;
            unpack2(acc[bb][g], lo, hi);
            if (do_relu) { lo = fmaxf(lo, 0.0f); hi = fmaxf(hi, 0.0f); }
            *(float2*)(C + (size_t)m * N + n0 + g * 32 + 2 * cc) = make_float2(lo, hi);
        }
    }
}

// ============================================================================
// fc2 head (R10-proven): 1.5 B/MAC tile, grid (250, 8), 128 thr.
// ============================================================================
__global__ __launch_bounds__(128)
void fc2_gemm(const float* __restrict__ W, const float* __restrict__ bias,
              float* __restrict__ C)
{
    __shared__ __align__(16) float sWn[32 * 132];
    __shared__ __align__(16) float sHm[32 * 34];
    const int t = threadIdx.x;
    const int n0 = blockIdx.x * 128, m0 = blockIdx.y * 32;
    const int tn = t & 31, tm = t >> 5;
    const int nb = tn * 4;
    const int kt = t & 7, rr = t >> 3;

    u64 acc[4][4];
    {
        float4 bv = *(const float4*)(bias + n0 + nb);
        u64 b0 = pack2(bv.x, bv.x), b1 = pack2(bv.y, bv.y);
        u64 b2 = pack2(bv.z, bv.z), b3 = pack2(bv.w, bv.w);
#pragma unroll
        for (int j = 0; j < 4; j++) {
            acc[0][j] = b0; acc[1][j] = b1; acc[2][j] = b2; acc[3][j] = b3;
        }
    }

#pragma unroll 1
    for (int kc = 0; kc < 32; kc++) {
        __syncthreads();
#pragma unroll
        for (int p = 0; p < 8; p++) {
            int n = rr + p * 16;
            float4 v = *(const float4*)(W + (size_t)(n0 + n) * 1024 + kc * 32 + kt * 4);
            sWn[(kt * 4 + 0) * 132 + n] = v.x;
            sWn[(kt * 4 + 1) * 132 + n] = v.y;
            sWn[(kt * 4 + 2) * 132 + n] = v.z;
            sWn[(kt * 4 + 3) * 132 + n] = v.w;
        }
#pragma unroll
        for (int p = 0; p < 2; p++) {
            int m = rr + p * 16;
            float4 v = *(const float4*)(g_z + (size_t)(m0 + m) * 1024 + kc * 32 + kt * 4);
            sHm[(kt * 4 + 0) * 34 + m] = v.x;
            sHm[(kt * 4 + 1) * 34 + m] = v.y;
            sHm[(kt * 4 + 2) * 34 + m] = v.z;
            sHm[(kt * 4 + 3) * 34 + m] = v.w;
        }
        __syncthreads();
#pragma unroll
        for (int kk = 0; kk < 32; kk++) {
            float4 wv = *(const float4*)(sWn + kk * 132 + nb);
            u64 h0 = *(const u64*)(sHm + kk * 34 + 2 * tm);
            u64 h1 = *(const u64*)(sHm + kk * 34 + 2 * (tm + 4));
            u64 h2 = *(const u64*)(sHm + kk * 34 + 2 * (tm + 8));
            u64 h3 = *(const u64*)(sHm + kk * 34 + 2 * (tm + 12));
            u64 w0 = pack2(wv.x, wv.x), w1 = pack2(wv.y, wv.y);
            u64 w2 = pack2(wv.z, wv.z), w3 = pack2(wv.w, wv.w);
            ffma2(acc[0][0], w0, h0); ffma2(acc[1][0], w1, h0);
            ffma2(acc[2][0], w2, h0); ffma2(acc[3][0], w3, h0);
            ffma2(acc[0][1], w0, h1); ffma2(acc[1][1], w1, h1);
            ffma2(acc[2][1], w2, h1); ffma2(acc[3][1], w3, h1);
            ffma2(acc[0][2], w0, h2); ffma2(acc[1][2], w1, h2);
            ffma2(acc[2][2], w2, h2); ffma2(acc[3][2], w3, h2);
            ffma2(acc[0][3], w0, h3); ffma2(acc[1][3], w1, h3);
            ffma2(acc[2][3], w2, h3); ffma2(acc[3][3], w3, h3);
        }
    }
#pragma unroll
    for (int j = 0; j < 4; j++) {
        int m = m0 + 2 * (tm + 4 * j);
        float l0, h0, l1, h1, l2, h2, l3, h3;
        unpack2(acc[0][j], l0, h0); unpack2(acc[1][j], l1, h1);
        unpack2(acc[2][j], l2, h2); unpack2(acc[3][j], l3, h3);
        *(float4*)(C + (size_t)m * FC2_N + n0 + nb)       = make_float4(l0, l1, l2, l3);
        *(float4*)(C + (size_t)(m + 1) * FC2_N + n0 + nb) = make_float4(h0, h1, h2, h3);
    }
}

// ============================================================================
extern "C" void kernel_launch(void* const* d_in, const int* in_sizes, int n_in,
                              void* d_out, int out_size) {
    const int*   trg   = (const int*)  d_in[2];
    const float* w_ih  = (const float*)d_in[3];
    const float* w_hh  = (const float*)d_in[4];
    const float* b_ih  = (const float*)d_in[5];
    const float* b_hh  = (const float*)d_in[6];
    const float* fc1_w = (const float*)d_in[7];
    const float* fc1_b = (const float*)d_in[8];
    const float* fc2_w = (const float*)d_in[9];
    const float* fc2_b = (const float*)d_in[10];
    float* out = (float*)d_out;

    cudaFuncSetAttribute(lstm_persist,
                         cudaFuncAttributeMaxDynamicSharedMemorySize, SMEMB);

    prep_w<<<4096, 256>>>(w_hh);                 // launch 1
    prep_misc<<<256, 256>>>();                   // launch 2
    nopk<<<1, 32>>>(0);                          // launch 3 (spacer)

    lstm_persist<<<128, 128, SMEMB>>>(trg, w_ih, b_ih, b_hh);   // launch 4 = ncu slot

    void* zsym = nullptr;
    cudaGetSymbolAddress(&zsym, g_z);
    float* zptr = (float*)zsym;
    fc_gemm<<<dim3(FC1_N / 128, BATCH / 32), 256>>>(0, fc1_w, fc1_b, zptr, HDIM, FC1_N, 1);
    fc2_gemm<<<dim3(FC2_N / 128, BATCH / 32), 128>>>(fc2_w, fc2_b, out);
}

// round 14
// speedup vs baseline: 1.2287x; 1.2287x over previous
#include <cuda_runtime.h>
#define HDIM 512
#define BATCH 256
#define TLEN 512
#define NSTEPS 511
#define FC1_N 1024
#define FC2_N 32000
typedef unsigned long long u64;

// -------- persistent device scratch --------
__device__ float g_wt[32 * 512 * 64];    // 4MB W: [kx][kk][kcol16][gate4] f32
__device__ u64   g_hp[2][512 * 128];     // h batch-pairs [k][pair], dbl-buffered
__device__ float g_hlast[BATCH * HDIM];
__device__ float g_z[BATCH * FC1_N];
__device__ unsigned int g_flag[128];     // write flags [by][kx]
__device__ int g_dummy;

__device__ __forceinline__ u64 pack2(float lo, float hi) {
    u64 r; asm("mov.b64 %0, {%1, %2};" : "=l"(r) : "f"(lo), "f"(hi)); return r;
}
__device__ __forceinline__ void unpack2(u64 v, float& lo, float& hi) {
    asm("mov.b64 {%0, %1}, %2;" : "=f"(lo), "=f"(hi) : "l"(v));
}
__device__ __forceinline__ void ffma2(u64& d, u64 a, u64 b) {
    asm("fma.rn.f32x2 %0, %1, %2, %0;" : "+l"(d) : "l"(a), "l"(b));
}
__device__ __forceinline__ u64 add2(u64 a, u64 b) {
    u64 r; asm("add.rn.f32x2 %0, %1, %2;" : "=l"(r) : "l"(a), "l"(b)); return r;
}
__device__ __forceinline__ ulonglong2 ldcg2(const u64* p) {
    ulonglong2 v;
    asm volatile("ld.global.cg.v2.u64 {%0,%1}, [%2];" : "=l"(v.x), "=l"(v.y) : "l"(p));
    return v;
}
__device__ __forceinline__ void stcg1(u64* p, u64 a) {
    asm volatile("st.global.cg.u64 [%0], %1;" :: "l"(p), "l"(a) : "memory");
}
__device__ __forceinline__ unsigned int ld_acq(const unsigned int* p) {
    unsigned int v;
    asm volatile("ld.global.acquire.gpu.b32 %0, [%1];" : "=r"(v) : "l"(p));
    return v;
}
__device__ __forceinline__ void st_rel(unsigned int* p, unsigned int v) {
    asm volatile("st.global.release.gpu.b32 [%0], %1;" :: "l"(p), "r"(v) : "memory");
}
// fast activations (MUFU; validated R12)
__device__ __forceinline__ float sigmoidf_(float x) {
    return 1.0f / (1.0f + __expf(-x));
}
__device__ __forceinline__ float tanhf_(float x) {
    return 1.0f - 2.0f / (__expf(2.0f * x) + 1.0f);
}

// ---- W transform (R9-proven) ----
__global__ void prep_w(const float* __restrict__ w) {
    int tid = blockIdx.x * blockDim.x + threadIdx.x;   // 0..1048575
    int g = tid & 3, kcol = (tid >> 2) & 15, kk = (tid >> 6) & 511, kx = tid >> 15;
    g_wt[tid] = w[(size_t)(g * HDIM + kx * 16 + kcol) * HDIM + kk];
}

__global__ void prep_misc() {
    int i = blockIdx.x * blockDim.x + threadIdx.x;
    int n = gridDim.x * blockDim.x;
    for (int j = i; j < 512 * 128; j += n) g_hp[0][j] = 0ull;
    if (i < 128) g_flag[i] = 0u;
}

// spacer: puts lstm_persist at launch #4 (the ncu capture slot)
__global__ void nopk(int v) { if (v == 12345) g_dummy = v; }

// ============================================================================
// Persistent LSTM, warp-half split-K (2 warps/SMSP, latency fix).
// 128 CTAs (32 kx x 4 by) x 256 thr, 1 CTA/SM. W resident in smem (131kB).
// Half z (128 thr, named bar 1+z) computes K chunks [8z, 8z+8) with its own
// smem h double-buffer; per-thread tile and inner loop identical to R12
// (1 kcol x 4 gates x 4 batch-pairs; LDS.128 w + 4 LDS.64 h + 16 FFMA2/kk).
// Entry gating per half on its OWN 16 producers only. Combine: half1 dumps
// accs into its vacated buffers; half0 pulls to regs, adds (f32x2), does
// pointwise + h stores + flag. c in half0 registers.
// ============================================================================
#define SW_F 32768                        // 512*64 f32
#define SMEMB (SW_F * 4 + 4 * 1024 * 8)   // 131072 + 32768 = 163840 B
__global__ __launch_bounds__(256, 1)
void lstm_persist(const int* __restrict__ trg,
                  const float* __restrict__ w_ih,
                  const float* __restrict__ b_ih,
                  const float* __restrict__ b_hh)
{
    extern __shared__ unsigned char smraw[];
    float* sW = (float*)smraw;                    // [512][16][4]
    u64*   sH = (u64*)(smraw + SW_F * 4);         // [4 buf][32 kk][32 pairs]

    const int t  = threadIdx.x;
    const int z  = t >> 7;                        // warp-half 0/1
    const int u  = t & 127;
    const int kx = blockIdx.x & 31, by = blockIdx.x >> 5;
    const int tk = u >> 3, tb = u & 7;
    const int kcol = kx * 16 + tk;
    const int bp0 = by * 32;
    const int kbase = z * 256;                    // this half's first kk
    u64* myH = sH + z * 2048;                     // two 1024-u64 buffers

    // load W slice once (coalesced, all 256 threads)
    {
        const float4* ws = (const float4*)(g_wt + (size_t)kx * SW_F);
        float4* wd = (float4*)sW;
        for (int i = t; i < SW_F / 4; i += 256) wd[i] = ws[i];
    }
    float bias[4], wih[4];
#pragma unroll
    for (int g = 0; g < 4; g++) {
        int r = g * HDIM + kcol;
        bias[g] = b_ih[r] + b_hh[r];
        wih[g]  = w_ih[r];
    }
    u64 cst[4] = {0ull, 0ull, 0ull, 0ull};        // c state (half0 only)
    __syncthreads();

#pragma unroll 1
    for (int s = 0; s < NSTEPS; s++) {
        const u64* __restrict__ hin  = g_hp[s & 1];
        u64*       __restrict__ hout = g_hp[(s & 1) ^ 1];

        // entry gate: each half waits only its own region's 16 producers
        if (s > 0) {
            if (u < 16) { while (ld_acq(&g_flag[by * 32 + z * 16 + u]) < (unsigned)s) { } }
            asm volatile("bar.sync %0, 128;" :: "r"(1 + z) : "memory");
        }

        // acc init: half0 carries bias + x*w_ih, half1 starts at 0
        u64 acc[4][4];
        if (z == 0) {
#pragma unroll
            for (int j = 0; j < 4; j++) {
                int b = (bp0 + tb + 8 * j) * 2;
                float x0 = (float)__ldg(trg + b * TLEN + s);
                float x1 = (float)__ldg(trg + (b + 1) * TLEN + s);
#pragma unroll
                for (int g = 0; g < 4; g++)
                    acc[g][j] = pack2(fmaf(x0, wih[g], bias[g]), fmaf(x1, wih[g], bias[g]));
            }
        } else {
#pragma unroll
            for (int g = 0; g < 4; g++)
#pragma unroll
                for (int j = 0; j < 4; j++) acc[g][j] = 0ull;
        }

        // prologue: this half's chunk 0 -> buf 0
        ulonglong2 pf[4];
#pragma unroll
        for (int q = 0; q < 4; q++) {
            int idx = q * 128 + u;
            pf[q] = ldcg2(hin + (size_t)(kbase + (idx >> 4)) * 128 + bp0 + (idx & 15) * 2);
        }
#pragma unroll
        for (int q = 0; q < 4; q++) {
            int idx = q * 128 + u;
            *(ulonglong2*)(myH + (idx >> 4) * 32 + (idx & 15) * 2) = pf[q];
        }
        asm volatile("bar.sync %0, 128;" :: "r"(1 + z) : "memory");

#pragma unroll 1
        for (int kc = 0; kc < 8; kc++) {
            if (kc < 7) {
#pragma unroll
                for (int q = 0; q < 4; q++) {
                    int idx = q * 128 + u;
                    pf[q] = ldcg2(hin + (size_t)(kbase + (kc + 1) * 32 + (idx >> 4)) * 128
                                  + bp0 + (idx & 15) * 2);
                }
            }
            const u64*   Hb = myH + (kc & 1) * 1024;
            const float* Wb = sW + (size_t)(kbase + kc * 32) * 64 + tk * 4;

            float4 wv = *(const float4*)(Wb);
            u64 h0 = Hb[tb], h1 = Hb[tb + 8], h2 = Hb[tb + 16], h3 = Hb[tb + 24];
#pragma unroll
            for (int kk = 0; kk < 32; kk++) {
                float4 wn;
                u64 n0, n1, n2, n3;
                if (kk < 31) {
                    wn = *(const float4*)(Wb + (kk + 1) * 64);
                    const u64* Hn = Hb + (kk + 1) * 32;
                    n0 = Hn[tb]; n1 = Hn[tb + 8]; n2 = Hn[tb + 16]; n3 = Hn[tb + 24];
                }
                u64 wd0 = pack2(wv.x, wv.x), wd1 = pack2(wv.y, wv.y);
                u64 wd2 = pack2(wv.z, wv.z), wd3 = pack2(wv.w, wv.w);
                ffma2(acc[0][0], wd0, h0); ffma2(acc[1][0], wd1, h0);
                ffma2(acc[2][0], wd2, h0); ffma2(acc[3][0], wd3, h0);
                ffma2(acc[0][1], wd0, h1); ffma2(acc[1][1], wd1, h1);
                ffma2(acc[2][1], wd2, h1); ffma2(acc[3][1], wd3, h1);
                ffma2(acc[0][2], wd0, h2); ffma2(acc[1][2], wd1, h2);
                ffma2(acc[2][2], wd2, h2); ffma2(acc[3][2], wd3, h2);
                ffma2(acc[0][3], wd0, h3); ffma2(acc[1][3], wd1, h3);
                ffma2(acc[2][3], wd2, h3); ffma2(acc[3][3], wd3, h3);
                if (kk < 31) { wv = wn; h0 = n0; h1 = n1; h2 = n2; h3 = n3; }
            }
            if (kc < 7) {
#pragma unroll
                for (int q = 0; q < 4; q++) {
                    int idx = q * 128 + u;
                    *(ulonglong2*)(myH + ((kc + 1) & 1) * 1024
                                   + (idx >> 4) * 32 + (idx & 15) * 2) = pf[q];
                }
            }
            asm volatile("bar.sync %0, 128;" :: "r"(1 + z) : "memory");
        }

        // ---- split-K combine (half1 buffers are free & reused) ----
        u64* af = &acc[0][0];
        if (z == 1) {
            ulonglong2* cb = (ulonglong2*)(sH + 2048);
#pragma unroll
            for (int p = 0; p < 8; p++)
                cb[p * 128 + u] = make_ulonglong2(af[2 * p], af[2 * p + 1]);
        }
        __syncthreads();
        u64 part[16];
        if (z == 0) {
            const ulonglong2* cb = (const ulonglong2*)(sH + 2048);
#pragma unroll
            for (int p = 0; p < 8; p++) {
                ulonglong2 v = cb[p * 128 + u];
                part[2 * p] = v.x; part[2 * p + 1] = v.y;
            }
        }
        __syncthreads();   // half1 may now race ahead; half0 has partials in regs

        if (z == 0) {
#pragma unroll
            for (int i = 0; i < 16; i++) af[i] = add2(af[i], part[i]);

            // ---- pointwise (i,f,g,o) ----
#pragma unroll
            for (int j = 0; j < 4; j++) {
                float i0, i1, f0, f1, g0, g1, o0, o1, c0, c1;
                unpack2(acc[0][j], i0, i1); unpack2(acc[1][j], f0, f1);
                unpack2(acc[2][j], g0, g1); unpack2(acc[3][j], o0, o1);
                unpack2(cst[j], c0, c1);
                i0 = sigmoidf_(i0); f0 = sigmoidf_(f0); g0 = tanhf_(g0); o0 = sigmoidf_(o0);
                i1 = sigmoidf_(i1); f1 = sigmoidf_(f1); g1 = tanhf_(g1); o1 = sigmoidf_(o1);
                c0 = fmaf(f0, c0, i0 * g0);
                c1 = fmaf(f1, c1, i1 * g1);
                cst[j] = pack2(c0, c1);
                float h0 = o0 * tanhf_(c0);
                float h1 = o1 * tanhf_(c1);
                stcg1(hout + (size_t)kcol * 128 + bp0 + tb + 8 * j, pack2(h0, h1));
                if (s == NSTEPS - 1) {
                    int b = (bp0 + tb + 8 * j) * 2;
                    g_hlast[(size_t)b * HDIM + kcol]       = h0;
                    g_hlast[(size_t)(b + 1) * HDIM + kcol] = h1;
                }
            }

            if (s < NSTEPS - 1) {
                asm volatile("bar.sync 1, 128;" ::: "memory");
                if (t == 0) {
                    __threadfence();
                    st_rel(&g_flag[by * 32 + kx], (unsigned)(s + 1));
                }
            }
        }
    }
}

// ============================================================================
// fc1 head (R3-proven fc_gemm): C = A @ W^T + bias, ReLU.
// ============================================================================
__global__ __launch_bounds__(256)
void fc_gemm(int asel, const float* __restrict__ W, const float* __restrict__ bias,
             float* __restrict__ C, int K, int N, int do_relu)
{
    __shared__ float  sW[32 * 128];
    __shared__ float2 sH2[32 * 33];
    const float* __restrict__ A = (asel == 0) ? &g_hlast[0] : &g_z[0];
    const int t = threadIdx.x, n0 = blockIdx.x * 128, m0 = blockIdx.y * 32;
    const int cc = t & 15, bi0 = (t >> 4) * 2;

    u64 acc[2][4];
#pragma unroll
    for (int g = 0; g < 4; g++) {
        float2 b2 = *(const float2*)(bias + n0 + g * 32 + 2 * cc);
        acc[0][g] = pack2(b2.x, b2.y);
        acc[1][g] = pack2(b2.x, b2.y);
    }
    const int r128 = t >> 1, hf = t & 1;
    const float4* __restrict__ Wrow = (const float4*)(W + (size_t)(n0 + r128) * K);
    const int hbi = t >> 3, hk0 = (t & 7) * 4;
    const u64* sWu = (const u64*)sW;
    const u64* sHu = (const u64*)sH2;

    for (int kc = 0; kc < K; kc += 32) {
        if (kc) __syncthreads();
#pragma unroll
        for (int q = 0; q < 4; q++) {
            float4 v = Wrow[(kc + hf * 16) / 4 + q];
            int kl = hf * 16 + q * 4;
            sW[(kl + 0) * 128 + r128] = v.x;
            sW[(kl + 1) * 128 + r128] = v.y;
            sW[(kl + 2) * 128 + r128] = v.z;
            sW[(kl + 3) * 128 + r128] = v.w;
        }
        float4 hv = *(const float4*)(A + (size_t)(m0 + hbi) * K + kc + hk0);
        sH2[(hk0 + 0) * 33 + hbi] = make_float2(hv.x, hv.x);
        sH2[(hk0 + 1) * 33 + hbi] = make_float2(hv.y, hv.y);
        sH2[(hk0 + 2) * 33 + hbi] = make_float2(hv.z, hv.z);
        sH2[(hk0 + 3) * 33 + hbi] = make_float2(hv.w, hv.w);
        __syncthreads();
#pragma unroll 8
        for (int kk = 0; kk < 32; kk++) {
            u64 h0 = sHu[kk * 33 + bi0];
            u64 h1 = sHu[kk * 33 + bi0 + 1];
#pragma unroll
            for (int g = 0; g < 4; g++) {
                u64 w = sWu[kk * 64 + g * 16 + cc];
                ffma2(acc[0][g], w, h0);
                ffma2(acc[1][g], w, h1);
            }
        }
    }
#pragma unroll
    for (int bb = 0; bb < 2; bb++) {
        int m = m0 + bi0 + bb;
#pragma unroll
        for (int g = 0; g < 4; g++) {
            float lo, hi;
            unpack2(acc[bb][g], lo, hi);
            if (do_relu) { lo = fmaxf(lo, 0.0f); hi = fmaxf(hi, 0.0f); }
            *(float2*)(C + (size_t)m * N + n0 + g * 32 + 2 * cc) = make_float2(lo, hi);
        }
    }
}

// ============================================================================
// fc2 head (R10-proven): 1.5 B/MAC tile, grid (250, 8), 128 thr.
// ============================================================================
__global__ __launch_bounds__(128)
void fc2_gemm(const float* __restrict__ W, const float* __restrict__ bias,
              float* __restrict__ C)
{
    __shared__ __align__(16) float sWn[32 * 132];
    __shared__ __align__(16) float sHm[32 * 34];
    const int t = threadIdx.x;
    const int n0 = blockIdx.x * 128, m0 = blockIdx.y * 32;
    const int tn = t & 31, tm = t >> 5;
    const int nb = tn * 4;
    const int kt = t & 7, rr = t >> 3;

    u64 acc[4][4];
    {
        float4 bv = *(const float4*)(bias + n0 + nb);
        u64 b0 = pack2(bv.x, bv.x), b1 = pack2(bv.y, bv.y);
        u64 b2 = pack2(bv.z, bv.z), b3 = pack2(bv.w, bv.w);
#pragma unroll
        for (int j = 0; j < 4; j++) {
            acc[0][j] = b0; acc[1][j] = b1; acc[2][j] = b2; acc[3][j] = b3;
        }
    }

#pragma unroll 1
    for (int kc = 0; kc < 32; kc++) {
        __syncthreads();
#pragma unroll
        for (int p = 0; p < 8; p++) {
            int n = rr + p * 16;
            float4 v = *(const float4*)(W + (size_t)(n0 + n) * 1024 + kc * 32 + kt * 4);
            sWn[(kt * 4 + 0) * 132 + n] = v.x;
            sWn[(kt * 4 + 1) * 132 + n] = v.y;
            sWn[(kt * 4 + 2) * 132 + n] = v.z;
            sWn[(kt * 4 + 3) * 132 + n] = v.w;
        }
#pragma unroll
        for (int p = 0; p < 2; p++) {
            int m = rr + p * 16;
            float4 v = *(const float4*)(g_z + (size_t)(m0 + m) * 1024 + kc * 32 + kt * 4);
            sHm[(kt * 4 + 0) * 34 + m] = v.x;
            sHm[(kt * 4 + 1) * 34 + m] = v.y;
            sHm[(kt * 4 + 2) * 34 + m] = v.z;
            sHm[(kt * 4 + 3) * 34 + m] = v.w;
        }
        __syncthreads();
#pragma unroll
        for (int kk = 0; kk < 32; kk++) {
            float4 wv = *(const float4*)(sWn + kk * 132 + nb);
            u64 h0 = *(const u64*)(sHm + kk * 34 + 2 * tm);
            u64 h1 = *(const u64*)(sHm + kk * 34 + 2 * (tm + 4));
            u64 h2 = *(const u64*)(sHm + kk * 34 + 2 * (tm + 8));
            u64 h3 = *(const u64*)(sHm + kk * 34 + 2 * (tm + 12));
            u64 w0 = pack2(wv.x, wv.x), w1 = pack2(wv.y, wv.y);
            u64 w2 = pack2(wv.z, wv.z), w3 = pack2(wv.w, wv.w);
            ffma2(acc[0][0], w0, h0); ffma2(acc[1][0], w1, h0);
            ffma2(acc[2][0], w2, h0); ffma2(acc[3][0], w3, h0);
            ffma2(acc[0][1], w0, h1); ffma2(acc[1][1], w1, h1);
            ffma2(acc[2][1], w2, h1); ffma2(acc[3][1], w3, h1);
            ffma2(acc[0][2], w0, h2); ffma2(acc[1][2], w1, h2);
            ffma2(acc[2][2], w2, h2); ffma2(acc[3][2], w3, h2);
            ffma2(acc[0][3], w0, h3); ffma2(acc[1][3], w1, h3);
            ffma2(acc[2][3], w2, h3); ffma2(acc[3][3], w3, h3);
        }
    }
#pragma unroll
    for (int j = 0; j < 4; j++) {
        int m = m0 + 2 * (tm + 4 * j);
        float l0, h0, l1, h1, l2, h2, l3, h3;
        unpack2(acc[0][j], l0, h0); unpack2(acc[1][j], l1, h1);
        unpack2(acc[2][j], l2, h2); unpack2(acc[3][j], l3, h3);
        *(float4*)(C + (size_t)m * FC2_N + n0 + nb)       = make_float4(l0, l1, l2, l3);
        *(float4*)(C + (size_t)(m + 1) * FC2_N + n0 + nb) = make_float4(h0, h1, h2, h3);
    }
}

// ============================================================================
extern "C" void kernel_launch(void* const* d_in, const int* in_sizes, int n_in,
                              void* d_out, int out_size) {
    const int*   trg   = (const int*)  d_in[2];
    const float* w_ih  = (const float*)d_in[3];
    const float* w_hh  = (const float*)d_in[4];
    const float* b_ih  = (const float*)d_in[5];
    const float* b_hh  = (const float*)d_in[6];
    const float* fc1_w = (const float*)d_in[7];
    const float* fc1_b = (const float*)d_in[8];
    const float* fc2_w = (const float*)d_in[9];
    const float* fc2_b = (const float*)d_in[10];
    float* out = (float*)d_out;

    cudaFuncSetAttribute(lstm_persist,
                         cudaFuncAttributeMaxDynamicSharedMemorySize, SMEMB);

    prep_w<<<4096, 256>>>(w_hh);                 // launch 1
    prep_misc<<<256, 256>>>();                   // launch 2
    nopk<<<1, 32>>>(0);                          // launch 3 (spacer)

    lstm_persist<<<128, 256, SMEMB>>>(trg, w_ih, b_ih, b_hh);   // launch 4 = ncu slot

    void* zsym = nullptr;
    cudaGetSymbolAddress(&zsym, g_z);
    float* zptr = (float*)zsym;
    fc_gemm<<<dim3(FC1_N / 128, BATCH / 32), 256>>>(0, fc1_w, fc1_b, zptr, HDIM, FC1_N, 1);
    fc2_gemm<<<dim3(FC2_N / 128, BATCH / 32), 128>>>(fc2_w, fc2_b, out);
}

// round 16
// speedup vs baseline: 1.7171x; 1.3976x over previous
#include <cuda_runtime.h>
#include <cuda_bf16.h>
#include <cstdint>
#define HDIM 512
#define BATCH 256
#define TLEN 512
#define NSTEPS 511
#define FC1_N 1024
#define FC2_N 32000
typedef unsigned long long u64;

// -------- persistent device scratch --------
__device__ uint2 g_wf[32 * 512 * 32];      // 4MB W B-fragments [kx][ks*16+nt*2+hl][lane]
__device__ uint4 g_ha[2][2][4][32][4][32]; // 2MB h A-fragments [buf][hl][by][ks][mt][lane]
__device__ float g_hlast[BATCH * HDIM];
__device__ float g_z[BATCH * FC1_N];
__device__ unsigned int g_flag[128];       // [by][kx]
__device__ int g_dummy;

__device__ __forceinline__ u64 pack2(float lo, float hi) {
    u64 r; asm("mov.b64 %0, {%1, %2};" : "=l"(r) : "f"(lo), "f"(hi)); return r;
}
__device__ __forceinline__ void unpack2(u64 v, float& lo, float& hi) {
    asm("mov.b64 {%0, %1}, %2;" : "=f"(lo), "=f"(hi) : "l"(v));
}
__device__ __forceinline__ void ffma2(u64& d, u64 a, u64 b) {
    asm("fma.rn.f32x2 %0, %1, %2, %0;" : "+l"(d) : "l"(a), "l"(b));
}
__device__ __forceinline__ uint4 ldcg4(const void* p) {
    uint4 v;
    asm volatile("ld.global.cg.v4.b32 {%0,%1,%2,%3}, [%4];"
                 : "=r"(v.x), "=r"(v.y), "=r"(v.z), "=r"(v.w) : "l"(p));
    return v;
}
__device__ __forceinline__ void stcg4(void* p, uint4 v) {
    asm volatile("st.global.cg.v4.b32 [%0], {%1,%2,%3,%4};"
                 :: "l"(p), "r"(v.x), "r"(v.y), "r"(v.z), "r"(v.w) : "memory");
}
__device__ __forceinline__ unsigned int ld_acq(const unsigned int* p) {
    unsigned int v;
    asm volatile("ld.global.acquire.gpu.b32 %0, [%1];" : "=r"(v) : "l"(p));
    return v;
}
__device__ __forceinline__ void st_rel(unsigned int* p, unsigned int v) {
    asm volatile("st.global.release.gpu.b32 [%0], %1;" :: "l"(p), "r"(v) : "memory");
}
__device__ __forceinline__ float sigmoidf_(float x) { return 1.0f / (1.0f + __expf(-x)); }
__device__ __forceinline__ float tanhf_(float x) { return 1.0f - 2.0f / (__expf(2.0f * x) + 1.0f); }
__device__ __forceinline__ unsigned short bfhi(float v) {
    return __bfloat16_as_ushort(__float2bfloat16(v));
}
__device__ __forceinline__ unsigned short bflo(float v) {
    __nv_bfloat16 h = __float2bfloat16(v);
    return __bfloat16_as_ushort(__float2bfloat16(v - __bfloat162float(h)));
}
// warp MMA: D[16m][8n] += A[16m][16k](bf16,row) * B[16k][8n](bf16,col), f32 acc
__device__ __forceinline__ void mma_bf16(float* d, const uint4& A, const uint2& B) {
    asm volatile("mma.sync.aligned.m16n8k16.row.col.f32.bf16.bf16.f32 "
                 "{%0,%1,%2,%3}, {%4,%5,%6,%7}, {%8,%9}, {%0,%1,%2,%3};"
                 : "+f"(d[0]), "+f"(d[1]), "+f"(d[2]), "+f"(d[3])
                 : "r"(A.x), "r"(A.y), "r"(A.z), "r"(A.w), "r"(B.x), "r"(B.y));
}

// ---- W -> B-fragment images (hi/lo split) ----
__global__ void prep_wf(const float* __restrict__ w) {
    int tid = blockIdx.x * blockDim.x + threadIdx.x;   // 0..524287
    int lane = tid & 31, q = tid >> 5;
    int hl = q & 1, nt = (q >> 1) & 7, ks = (q >> 4) & 31, kx = q >> 9;
    int g = lane >> 2, tc = lane & 3;
    int gate = nt >> 1, j = (nt & 1) * 8 + g;
    const float* row = w + (size_t)(gate * HDIM + kx * 16 + j) * HDIM;
    int k0 = ks * 16 + tc * 2;
    float v00 = row[k0], v01 = row[k0 + 1], v10 = row[k0 + 8], v11 = row[k0 + 9];
    unsigned short b00 = hl ? bflo(v00) : bfhi(v00);
    unsigned short b01 = hl ? bflo(v01) : bfhi(v01);
    unsigned short b10 = hl ? bflo(v10) : bfhi(v10);
    unsigned short b11 = hl ? bflo(v11) : bfhi(v11);
    uint2 r;
    r.x = (unsigned)b00 | ((unsigned)b01 << 16);
    r.y = (unsigned)b10 | ((unsigned)b11 << 16);
    g_wf[tid] = r;
}

__global__ void prep_misc() {
    int i = blockIdx.x * blockDim.x + threadIdx.x;
    int n = gridDim.x * blockDim.x;
    uint4 z = make_uint4(0, 0, 0, 0);
    uint4* ha = &g_ha[0][0][0][0][0][0];
    for (int j = i; j < 2 * 2 * 4 * 32 * 4 * 32; j += n) ha[j] = z;
    if (i < 128) g_flag[i] = 0u;
}

// spacer: puts lstm_mma at launch #4 (the ncu capture slot)
__global__ void nopk(int v) { if (v == 12345) g_dummy = v; }

// ============================================================================
// Persistent HMMA LSTM. 128 CTAs (32 kx x 4 by) x 128 thr, 1 CTA/SM.
// CTA: D[64 batch][64 n], n = gate*16 + kcol; K = 512 (32 k-steps of 16).
// Warp w owns gate w (n-tiles 2w, 2w+1) x all 4 m-tiles; acc in registers.
// W resident in smem as B-fragments (hi+lo, 128kB). h exchanged via global
// A-fragment images (.cg), staged per 4-kstep chunk through smem (dbl buf).
// 3 MMA terms/kstep (hh + lh + hl). Pointwise via 17kB smem D exchange.
// ============================================================================
#define SM_A  131072
#define SM_D  163840
#define SM_BW 180736
#define SMEMB 181248
__global__ __launch_bounds__(128, 1)
void lstm_mma(const int* __restrict__ trg,
              const float* __restrict__ w_ih,
              const float* __restrict__ b_ih,
              const float* __restrict__ b_hh)
{
    extern __shared__ char sm[];
    uint2* sWB = (uint2*)sm;                  // [512][32] fragments
    uint4* sA  = (uint4*)(sm + SM_A);         // [2 buf][4ksl*4mt*2hl][32 lane]
    float* sD  = (float*)(sm + SM_D);         // [64 m][66 pitch]
    float* sbw = (float*)(sm + SM_BW);        // [64 bias | 64 wih]

    const int t = threadIdx.x;
    const int kx = blockIdx.x & 31, by = blockIdx.x >> 5;
    const int b0 = by * 64;
    const int w = t >> 5, lane = t & 31;
    const int g = lane >> 2, tc = lane & 3;

    // load W fragment slice (16384 uint2 = 128kB), coalesced
    {
        const uint2* ws = g_wf + (size_t)kx * 16384;
        for (int i = t; i < 16384; i += 128) sWB[i] = ws[i];
    }
    if (t < 64) {
        int gate = t >> 4, j = t & 15;
        int row = gate * HDIM + kx * 16 + j;
        sbw[t]      = b_ih[row] + b_hh[row];
        sbw[64 + t] = w_ih[row];
    }
    float cst[2][4];
#pragma unroll
    for (int a = 0; a < 2; a++)
#pragma unroll
        for (int bq = 0; bq < 4; bq++) cst[a][bq] = 0.0f;
    __syncthreads();

#pragma unroll 1
    for (int s = 0; s < NSTEPS; s++) {
        // entry gate: all 32 producers of my by-group finished step s-1
        if (s > 0) {
            if (t < 32) { while (ld_acq(&g_flag[by * 32 + t]) < (unsigned)s) { } }
            __syncthreads();
        }

        float acc[2][4][4];   // [ntl][mt][reg]
#pragma unroll
        for (int a = 0; a < 2; a++)
#pragma unroll
            for (int m = 0; m < 4; m++)
#pragma unroll
                for (int r = 0; r < 4; r++) acc[a][m][r] = 0.0f;

        uint4 pf[8];
#define LDG_CHUNK(c) do {                                                     \
        _Pragma("unroll")                                                     \
        for (int q = 0; q < 8; q++) {                                         \
            int fl = q * 128 + t;                                             \
            int l2 = fl & 31, hl = (fl >> 5) & 1, mq = (fl >> 6) & 3,         \
                kl = fl >> 8;                                                 \
            pf[q] = ldcg4(&g_ha[s & 1][hl][by][(c) * 4 + kl][mq][l2]);        \
        } } while (0)
#define STS_CHUNK(buf) do {                                                   \
        _Pragma("unroll")                                                     \
        for (int q = 0; q < 8; q++) {                                         \
            int fl = q * 128 + t;                                             \
            int l2 = fl & 31, hl = (fl >> 5) & 1, mq = (fl >> 6) & 3,         \
                kl = fl >> 8;                                                 \
            sA[(buf) * 1024 + ((kl * 4 + mq) * 2 + hl) * 32 + l2] = pf[q];    \
        } } while (0)

        LDG_CHUNK(0);
        STS_CHUNK(0);
        __syncthreads();

#pragma unroll 1
        for (int c = 0; c < 8; c++) {
            if (c < 7) LDG_CHUNK(c + 1);
            const uint4* Ab = sA + (c & 1) * 1024;
#pragma unroll
            for (int kl = 0; kl < 4; kl++) {
                int ks = c * 4 + kl;
                uint4 ah[4], al[4];
#pragma unroll
                for (int m = 0; m < 4; m++) {
                    ah[m] = Ab[((kl * 4 + m) * 2 + 0) * 32 + lane];
                    al[m] = Ab[((kl * 4 + m) * 2 + 1) * 32 + lane];
                }
                uint2 bh[2], bl[2];
#pragma unroll
                for (int nl = 0; nl < 2; nl++) {
                    int nt = w * 2 + nl;
                    bh[nl] = sWB[(ks * 16 + nt * 2 + 0) * 32 + lane];
                    bl[nl] = sWB[(ks * 16 + nt * 2 + 1) * 32 + lane];
                }
#pragma unroll
                for (int nl = 0; nl < 2; nl++)
#pragma unroll
                    for (int m = 0; m < 4; m++) {
                        mma_bf16(acc[nl][m], ah[m], bh[nl]);
                        mma_bf16(acc[nl][m], al[m], bh[nl]);
                        mma_bf16(acc[nl][m], ah[m], bl[nl]);
                    }
            }
            if (c < 7) STS_CHUNK((c + 1) & 1);
            __syncthreads();
        }

        // ---- D exchange: acc fragments -> sD[m][n] (pitch 66) ----
#pragma unroll
        for (int nl = 0; nl < 2; nl++)
#pragma unroll
            for (int m = 0; m < 4; m++) {
                int n0 = w * 16 + nl * 8 + 2 * tc;
                int mm = m * 16 + g;
                *(float2*)&sD[mm * 66 + n0] =
                    make_float2(acc[nl][m][0], acc[nl][m][1]);
                *(float2*)&sD[(mm + 8) * 66 + n0] =
                    make_float2(acc[nl][m][2], acc[nl][m][3]);
            }
        __syncthreads();

        // ---- pointwise: thread owns (mt=w, lane) A-fragment positions ----
        const int mt = w;
        float hv[2][4];
#pragma unroll
        for (int rr = 0; rr < 2; rr++) {
            int m = mt * 16 + g + rr * 8;
            float x = (float)__ldg(trg + (size_t)(b0 + m) * TLEN + s);
#pragma unroll
            for (int jj = 0; jj < 4; jj++) {
                int j = 2 * tc + (jj & 1) + (jj >> 1) * 8;
                float gi = sD[m * 66 + 0 * 16 + j] + sbw[0 * 16 + j] + x * sbw[64 + 0 * 16 + j];
                float gf = sD[m * 66 + 1 * 16 + j] + sbw[1 * 16 + j] + x * sbw[64 + 1 * 16 + j];
                float gg = sD[m * 66 + 2 * 16 + j] + sbw[2 * 16 + j] + x * sbw[64 + 2 * 16 + j];
                float go = sD[m * 66 + 3 * 16 + j] + sbw[3 * 16 + j] + x * sbw[64 + 3 * 16 + j];
                float iv = sigmoidf_(gi), fv = sigmoidf_(gf);
                float gv = tanhf_(gg),   ov = sigmoidf_(go);
                float cn = fmaf(fv, cst[rr][jj], iv * gv);
                cst[rr][jj] = cn;
                hv[rr][jj] = ov * tanhf_(cn);
            }
        }
        // pack h into A-fragments (hi/lo) and store for next step
        {
            uint4 hi4, lo4;
            hi4.x = (unsigned)bfhi(hv[0][0]) | ((unsigned)bfhi(hv[0][1]) << 16);
            hi4.y = (unsigned)bfhi(hv[1][0]) | ((unsigned)bfhi(hv[1][1]) << 16);
            hi4.z = (unsigned)bfhi(hv[0][2]) | ((unsigned)bfhi(hv[0][3]) << 16);
            hi4.w = (unsigned)bfhi(hv[1][2]) | ((unsigned)bfhi(hv[1][3]) << 16);
            lo4.x = (unsigned)bflo(hv[0][0]) | ((unsigned)bflo(hv[0][1]) << 16);
            lo4.y = (unsigned)bflo(hv[1][0]) | ((unsigned)bflo(hv[1][1]) << 16);
            lo4.z = (unsigned)bflo(hv[0][2]) | ((unsigned)bflo(hv[0][3]) << 16);
            lo4.w = (unsigned)bflo(hv[1][2]) | ((unsigned)bflo(hv[1][3]) << 16);
            stcg4(&g_ha[(s & 1) ^ 1][0][by][kx][mt][lane], hi4);
            stcg4(&g_ha[(s & 1) ^ 1][1][by][kx][mt][lane], lo4);
        }
        if (s == NSTEPS - 1) {
#pragma unroll
            for (int rr = 0; rr < 2; rr++)
#pragma unroll
                for (int jj = 0; jj < 4; jj++) {
                    int j = 2 * tc + (jj & 1) + (jj >> 1) * 8;
                    int b = b0 + mt * 16 + g + rr * 8;
                    g_hlast[(size_t)b * HDIM + kx * 16 + j] = hv[rr][jj];
                }
        }

        if (s < NSTEPS - 1) {
            __syncthreads();
            if (t == 0) {
                __threadfence();
                st_rel(&g_flag[by * 32 + kx], (unsigned)(s + 1));
            }
        }
    }
}

// ============================================================================
// fc1 head (R3-proven): C = A @ W^T + bias, ReLU.
// ============================================================================
__global__ __launch_bounds__(256)
void fc_gemm(int asel, const float* __restrict__ W, const float* __restrict__ bias,
             float* __restrict__ C, int K, int N, int do_relu)
{
    __shared__ float  sW[32 * 128];
    __shared__ float2 sH2[32 * 33];
    const float* __restrict__ A = (asel == 0) ? &g_hlast[0] : &g_z[0];
    const int t = threadIdx.x, n0 = blockIdx.x * 128, m0 = blockIdx.y * 32;
    const int cc = t & 15, bi0 = (t >> 4) * 2;

    u64 acc[2][4];
#pragma unroll
    for (int g = 0; g < 4; g++) {
        float2 b2 = *(const float2*)(bias + n0 + g * 32 + 2 * cc);
        acc[0][g] = pack2(b2.x, b2.y);
        acc[1][g] = pack2(b2.x, b2.y);
    }
    const int r128 = t >> 1, hf = t & 1;
    const float4* __restrict__ Wrow = (const float4*)(W + (size_t)(n0 + r128) * K);
    const int hbi = t >> 3, hk0 = (t & 7) * 4;
    const u64* sWu = (const u64*)sW;
    const u64* sHu = (const u64*)sH2;

    for (int kc = 0; kc < K; kc += 32) {
        if (kc) __syncthreads();
#pragma unroll
        for (int q = 0; q < 4; q++) {
            float4 v = Wrow[(kc + hf * 16) / 4 + q];
            int kl = hf * 16 + q * 4;
            sW[(kl + 0) * 128 + r128] = v.x;
            sW[(kl + 1) * 128 + r128] = v.y;
            sW[(kl + 2) * 128 + r128] = v.z;
            sW[(kl + 3) * 128 + r128] = v.w;
        }
        float4 hv = *(const float4*)(A + (size_t)(m0 + hbi) * K + kc + hk0);
        sH2[(hk0 + 0) * 33 + hbi] = make_float2(hv.x, hv.x);
        sH2[(hk0 + 1) * 33 + hbi] = make_float2(hv.y, hv.y);
        sH2[(hk0 + 2) * 33 + hbi] = make_float2(hv.z, hv.z);
        sH2[(hk0 + 3) * 33 + hbi] = make_float2(hv.w, hv.w);
        __syncthreads();
#pragma unroll 8
        for (int kk = 0; kk < 32; kk++) {
            u64 h0 = sHu[kk * 33 + bi0];
            u64 h1 = sHu[kk * 33 + bi0 + 1];
#pragma unroll
            for (int g = 0; g < 4; g++) {
                u64 w = sWu[kk * 64 + g * 16 + cc];
                ffma2(acc[0][g], w, h0);
                ffma2(acc[1][g], w, h1);
            }
        }
    }
#pragma unroll
    for (int bb = 0; bb < 2; bb++) {
        int m = m0 + bi0 + bb;
#pragma unroll
        for (int g = 0; g < 4; g++) {
            float lo, hi;
            unpack2(acc[bb][g], lo, hi);
            if (do_relu) { lo = fmaxf(lo, 0.0f); hi = fmaxf(hi, 0.0f); }
            *(float2*)(C + (size_t)m * N + n0 + g * 32 + 2 * cc) = make_float2(lo, hi);
        }
    }
}

// ============================================================================
// fc2 head (R10-proven): 1.5 B/MAC tile, grid (250, 8), 128 thr.
// ============================================================================
__global__ __launch_bounds__(128)
void fc2_gemm(const float* __restrict__ W, const float* __restrict__ bias,
              float* __restrict__ C)
{
    __shared__ __align__(16) float sWn[32 * 132];
    __shared__ __align__(16) float sHm[32 * 34];
    const int t = threadIdx.x;
    const int n0 = blockIdx.x * 128, m0 = blockIdx.y * 32;
    const int tn = t & 31, tm = t >> 5;
    const int nb = tn * 4;
    const int kt = t & 7, rr = t >> 3;

    u64 acc[4][4];
    {
        float4 bv = *(const float4*)(bias + n0 + nb);
        u64 b0 = pack2(bv.x, bv.x), b1 = pack2(bv.y, bv.y);
        u64 b2 = pack2(bv.z, bv.z), b3 = pack2(bv.w, bv.w);
#pragma unroll
        for (int j = 0; j < 4; j++) {
            acc[0][j] = b0; acc[1][j] = b1; acc[2][j] = b2; acc[3][j] = b3;
        }
    }

#pragma unroll 1
    for (int kc = 0; kc < 32; kc++) {
        __syncthreads();
#pragma unroll
        for (int p = 0; p < 8; p++) {
            int n = rr + p * 16;
            float4 v = *(const float4*)(W + (size_t)(n0 + n) * 1024 + kc * 32 + kt * 4);
            sWn[(kt * 4 + 0) * 132 + n] = v.x;
            sWn[(kt * 4 + 1) * 132 + n] = v.y;
            sWn[(kt * 4 + 2) * 132 + n] = v.z;
            sWn[(kt * 4 + 3) * 132 + n] = v.w;
        }
#pragma unroll
        for (int p = 0; p < 2; p++) {
            int m = rr + p * 16;
            float4 v = *(const float4*)(g_z + (size_t)(m0 + m) * 1024 + kc * 32 + kt * 4);
            sHm[(kt * 4 + 0) * 34 + m] = v.x;
            sHm[(kt * 4 + 1) * 34 + m] = v.y;
            sHm[(kt * 4 + 2) * 34 + m] = v.z;
            sHm[(kt * 4 + 3) * 34 + m] = v.w;
        }
        __syncthreads();
#pragma unroll
        for (int kk = 0; kk < 32; kk++) {
            float4 wv = *(const float4*)(sWn + kk * 132 + nb);
            u64 h0 = *(const u64*)(sHm + kk * 34 + 2 * tm);
            u64 h1 = *(const u64*)(sHm + kk * 34 + 2 * (tm + 4));
            u64 h2 = *(const u64*)(sHm + kk * 34 + 2 * (tm + 8));
            u64 h3 = *(const u64*)(sHm + kk * 34 + 2 * (tm + 12));
            u64 w0 = pack2(wv.x, wv.x), w1 = pack2(wv.y, wv.y);
            u64 w2 = pack2(wv.z, wv.z), w3 = pack2(wv.w, wv.w);
            ffma2(acc[0][0], w0, h0); ffma2(acc[1][0], w1, h0);
            ffma2(acc[2][0], w2, h0); ffma2(acc[3][0], w3, h0);
            ffma2(acc[0][1], w0, h1); ffma2(acc[1][1], w1, h1);
            ffma2(acc[2][1], w2, h1); ffma2(acc[3][1], w3, h1);
            ffma2(acc[0][2], w0, h2); ffma2(acc[1][2], w1, h2);
            ffma2(acc[2][2], w2, h2); ffma2(acc[3][2], w3, h2);
            ffma2(acc[0][3], w0, h3); ffma2(acc[1][3], w1, h3);
            ffma2(acc[2][3], w2, h3); ffma2(acc[3][3], w3, h3);
        }
    }
#pragma unroll
    for (int j = 0; j < 4; j++) {
        int m = m0 + 2 * (tm + 4 * j);
        float l0, h0, l1, h1, l2, h2, l3, h3;
        unpack2(acc[0][j], l0, h0); unpack2(acc[1][j], l1, h1);
        unpack2(acc[2][j], l2, h2); unpack2(acc[3][j], l3, h3);
        *(float4*)(C + (size_t)m * FC2_N + n0 + nb)       = make_float4(l0, l1, l2, l3);
        *(float4*)(C + (size_t)(m + 1) * FC2_N + n0 + nb) = make_float4(h0, h1, h2, h3);
    }
}

// ============================================================================
extern "C" void kernel_launch(void* const* d_in, const int* in_sizes, int n_in,
                              void* d_out, int out_size) {
    const int*   trg   = (const int*)  d_in[2];
    const float* w_ih  = (const float*)d_in[3];
    const float* w_hh  = (const float*)d_in[4];
    const float* b_ih  = (const float*)d_in[5];
    const float* b_hh  = (const float*)d_in[6];
    const float* fc1_w = (const float*)d_in[7];
    const float* fc1_b = (const float*)d_in[8];
    const float* fc2_w = (const float*)d_in[9];
    const float* fc2_b = (const float*)d_in[10];
    float* out = (float*)d_out;

    cudaFuncSetAttribute(lstm_mma,
                         cudaFuncAttributeMaxDynamicSharedMemorySize, SMEMB);

    prep_wf<<<2048, 256>>>(w_hh);                         // launch 1
    prep_misc<<<256, 256>>>();                            // launch 2
    nopk<<<1, 32>>>(0);                                   // launch 3 (spacer)

    lstm_mma<<<128, 128, SMEMB>>>(trg, w_ih, b_ih, b_hh); // launch 4 = ncu slot

    void* zsym = nullptr;
    cudaGetSymbolAddress(&zsym, g_z);
    float* zptr = (float*)zsym;
    fc_gemm<<<dim3(FC1_N / 128, BATCH / 32), 256>>>(0, fc1_w, fc1_b, zptr, HDIM, FC1_N, 1);
    fc2_gemm<<<dim3(FC2_N / 128, BATCH / 32), 128>>>(fc2_w, fc2_b, out);
}